// round 7
// baseline (speedup 1.0000x reference)
#include <cuda_runtime.h>
#include <cuda_fp16.h>
#include <math.h>
#include <stdint.h>

#define TT 2048
#define SS 2048
#define BB 16
#define DD 1024
#define KK2 2048

// ---------------- device scratch (static) ----------------
__device__ float  g_scores[(size_t)BB * TT * SS];   // 256 MiB
__device__ __half g_combH[(size_t)BB * TT * KK2];   // [b][t][0..1023]=mix, [1024..2047]=q
__device__ __half g_combL[(size_t)BB * TT * KK2];
__device__ __half g_cH[(size_t)BB * SS * DD];       // context hi [b][s][d]
__device__ __half g_cL[(size_t)BB * SS * DD];
__device__ __half g_cTH[(size_t)BB * DD * SS];      // context^T [b][d][s]
__device__ __half g_cTL[(size_t)BB * DD * SS];
__device__ __half g_PH[(size_t)BB * TT * SS];       // probs hi/lo
__device__ __half g_PL[(size_t)BB * TT * SS];
__device__ __half g_WH[(size_t)DD * KK2];
__device__ __half g_WL[(size_t)DD * KK2];

// ---------------- helpers ----------------
__device__ __forceinline__ void split2(float x, __half& h, __half& l) {
    h = __float2half_rn(x);
    l = __float2half_rn(x - __half2float(h));
}

__device__ __forceinline__ uint32_t smem_u32(const void* p) {
    uint32_t a;
    asm("{ .reg .u64 t; cvta.to.shared.u64 t, %1; cvt.u32.u64 %0, t; }" : "=r"(a) : "l"(p));
    return a;
}

__device__ __forceinline__ void ldsm4(uint32_t* r, uint32_t addr) {
    asm volatile("ldmatrix.sync.aligned.m8n8.x4.shared.b16 {%0,%1,%2,%3}, [%4];"
                 : "=r"(r[0]), "=r"(r[1]), "=r"(r[2]), "=r"(r[3]) : "r"(addr));
}

__device__ __forceinline__ void mma_f16(float* c, const uint32_t* a, uint32_t b0, uint32_t b1) {
    asm volatile(
        "mma.sync.aligned.m16n8k16.row.col.f32.f16.f16.f32 "
        "{%0,%1,%2,%3}, {%4,%5,%6,%7}, {%8,%9}, {%0,%1,%2,%3};"
        : "+f"(c[0]), "+f"(c[1]), "+f"(c[2]), "+f"(c[3])
        : "r"(a[0]), "r"(a[1]), "r"(a[2]), "r"(a[3]), "r"(b0), "r"(b1));
}

// 64B logical rows (K=32 fp16), 2 rows per 128B line, 8-sub XOR swizzle
__device__ __forceinline__ uint32_t sw_off(int r, int c16) {
    uint32_t line = (uint32_t)(r >> 1);
    uint32_t sub = (uint32_t)(c16 + ((r & 1) << 2));
    return (line << 7) + ((sub ^ (line & 7)) << 4);
}

// ---------------- fused split-precision fp16 mma.sync GEMM ----------------
// One K sweep; per 32-K chunk loads Ah, Al, Bh(, Bl) and accumulates:
//   NP=3: Ah*Bh + Al*Bh + Ah*Bl      NP=2: Ah*Bh + Al*Bh
// CTA tile M128 x N256, 16 warps (4x4 grid, warp tile 32x64), 1 CTA/SM.
// EPI: 0=fp32 store, 1=fp16 hi/lo store, 2=bias+tanh fp32.
#define A_TILE_B 8192
#define B_TILE_B 16384
#define SMEM_NP3 (3 * (2 * A_TILE_B + 2 * B_TILE_B))  // 144KB
#define SMEM_NP2 (4 * (2 * A_TILE_B + 1 * B_TILE_B))  // 128KB

template <int EPI, int NP>
__global__ __launch_bounds__(512, 1) void mma_gemm(
    const __half* __restrict__ Ah, const __half* __restrict__ Al,
    size_t a_row, size_t a_batch,
    const __half* __restrict__ Bh, const __half* __restrict__ Bl,
    size_t b_row, size_t b_batch,
    int KCH,  // K/32
    float* __restrict__ outF, __half* __restrict__ outH, __half* __restrict__ outL,
    size_t c_row, size_t c_batch, const float* __restrict__ bias) {
    constexpr int NSTG = (NP == 3) ? 3 : 4;
    constexpr uint32_t STAGE_B = (NP == 3) ? (2 * A_TILE_B + 2 * B_TILE_B)
                                           : (2 * A_TILE_B + 1 * B_TILE_B);
    constexpr uint32_t AH_OFF = 0, AL_OFF = A_TILE_B, BH_OFF = 2 * A_TILE_B,
                       BL_OFF = 2 * A_TILE_B + B_TILE_B;

    extern __shared__ char smem[];
    const uint32_t sb = smem_u32(smem);
    const int tid = threadIdx.x;
    const int lane = tid & 31, wid = tid >> 5;
    const int wm = wid & 3, wn = wid >> 2;  // 4x4 warp grid
    const int n0 = blockIdx.x * 256, m0 = blockIdx.y * 128, bz = blockIdx.z;

    const __half* A_h = Ah + (size_t)bz * a_batch + (size_t)m0 * a_row;
    const __half* A_l = Al + (size_t)bz * a_batch + (size_t)m0 * a_row;
    const __half* B_h = Bh + (size_t)bz * b_batch + (size_t)n0 * b_row;
    const __half* B_l = (NP == 3) ? (Bl + (size_t)bz * b_batch + (size_t)n0 * b_row) : nullptr;

    auto load_tileA = [&](uint32_t dst, const __half* g, size_t rstride, int kk) {
        // 128 rows x 32 cols = 512 16B chunks, 512 threads -> 1 each
        const int r = tid >> 2, cc = tid & 3;
        const char* gp = (const char*)(g + (size_t)r * rstride + kk) + (cc << 4);
        asm volatile("cp.async.cg.shared.global [%0], [%1], 16;"
                     :: "r"(dst + sw_off(r, cc)), "l"(gp) : "memory");
    };
    auto load_tileB = [&](uint32_t dst, const __half* g, size_t rstride, int kk) {
        // 256 rows x 32 cols = 1024 chunks -> 2 each
#pragma unroll
        for (int i = tid; i < 1024; i += 512) {
            const int r = i >> 2, cc = i & 3;
            const char* gp = (const char*)(g + (size_t)r * rstride + kk) + (cc << 4);
            asm volatile("cp.async.cg.shared.global [%0], [%1], 16;"
                         :: "r"(dst + sw_off(r, cc)), "l"(gp) : "memory");
        }
    };
    auto load_stage = [&](int c) {
        const int kk = c * 32;
        const uint32_t st = sb + (uint32_t)(c % NSTG) * STAGE_B;
        load_tileA(st + AH_OFF, A_h, a_row, kk);
        load_tileA(st + AL_OFF, A_l, a_row, kk);
        load_tileB(st + BH_OFF, B_h, b_row, kk);
        if (NP == 3) load_tileB(st + BL_OFF, B_l, b_row, kk);
        asm volatile("cp.async.commit_group;" ::: "memory");
    };

    // per-thread ldmatrix offsets (k16 step via XOR 0x20)
    uint32_t offA[2], offB[4];
    {
        const int gA = lane >> 4;
#pragma unroll
        for (int mi = 0; mi < 2; mi++)
            offA[mi] = sw_off(wm * 32 + mi * 16 + (lane & 15), gA);
        const int gB = (lane >> 3) & 1;
        const int rb = wn * 64 + ((lane >> 4) << 3) + (lane & 7);
#pragma unroll
        for (int nj = 0; nj < 4; nj++) offB[nj] = sw_off(rb + nj * 16, gB);
    }

    float acc[2][8][4];
#pragma unroll
    for (int i = 0; i < 2; i++)
#pragma unroll
        for (int j = 0; j < 8; j++)
#pragma unroll
            for (int q = 0; q < 4; q++) acc[i][j][q] = 0.0f;

#pragma unroll
    for (int s = 0; s < NSTG - 1; s++) load_stage(s);

    for (int c = 0; c < KCH; c++) {
        asm volatile("cp.async.wait_group %0;" :: "n"(NSTG - 2) : "memory");
        __syncthreads();
        if (c + NSTG - 1 < KCH) load_stage(c + NSTG - 1);
        else asm volatile("cp.async.commit_group;" ::: "memory");

        const uint32_t st = sb + (uint32_t)(c % NSTG) * STAGE_B;
#pragma unroll
        for (int k16 = 0; k16 < 2; k16++) {
            const uint32_t x = (uint32_t)(k16 << 5);
            uint32_t ah[2][4], al[2][4];
            ldsm4(ah[0], st + AH_OFF + (offA[0] ^ x));
            ldsm4(ah[1], st + AH_OFF + (offA[1] ^ x));
            ldsm4(al[0], st + AL_OFF + (offA[0] ^ x));
            ldsm4(al[1], st + AL_OFF + (offA[1] ^ x));
#pragma unroll
            for (int nj = 0; nj < 4; nj++) {
                uint32_t bh[4];
                ldsm4(bh, st + BH_OFF + (offB[nj] ^ x));
                mma_f16(acc[0][2 * nj], ah[0], bh[0], bh[1]);
                mma_f16(acc[0][2 * nj + 1], ah[0], bh[2], bh[3]);
                mma_f16(acc[1][2 * nj], ah[1], bh[0], bh[1]);
                mma_f16(acc[1][2 * nj + 1], ah[1], bh[2], bh[3]);
                mma_f16(acc[0][2 * nj], al[0], bh[0], bh[1]);
                mma_f16(acc[0][2 * nj + 1], al[0], bh[2], bh[3]);
                mma_f16(acc[1][2 * nj], al[1], bh[0], bh[1]);
                mma_f16(acc[1][2 * nj + 1], al[1], bh[2], bh[3]);
                if (NP == 3) {
                    uint32_t bl[4];
                    ldsm4(bl, st + BL_OFF + (offB[nj] ^ x));
                    mma_f16(acc[0][2 * nj], ah[0], bl[0], bl[1]);
                    mma_f16(acc[0][2 * nj + 1], ah[0], bl[2], bl[3]);
                    mma_f16(acc[1][2 * nj], ah[1], bl[0], bl[1]);
                    mma_f16(acc[1][2 * nj + 1], ah[1], bl[2], bl[3]);
                }
            }
        }
    }

    // -------- epilogue --------
    const int trow = lane >> 2, tcol = (lane & 3) * 2;
#pragma unroll
    for (int mi = 0; mi < 2; mi++) {
#pragma unroll
        for (int nj = 0; nj < 8; nj++) {
            const int row = m0 + wm * 32 + mi * 16 + trow;
            const int col = n0 + wn * 64 + nj * 8 + tcol;
            const float* a4 = acc[mi][nj];
            if (EPI == 0) {
                float* p = outF + (size_t)bz * c_batch + (size_t)row * c_row + col;
                *(float2*)p = make_float2(a4[0], a4[1]);
                *(float2*)(p + 8 * c_row) = make_float2(a4[2], a4[3]);
            } else if (EPI == 1) {
                __half* ph = outH + (size_t)bz * c_batch + (size_t)row * c_row + col;
                __half* pl = outL + (size_t)bz * c_batch + (size_t)row * c_row + col;
                __half h0, l0, h1, l1;
                split2(a4[0], h0, l0);
                split2(a4[1], h1, l1);
                __half2 vh, vl;
                vh.x = h0; vh.y = h1; vl.x = l0; vl.y = l1;
                *(__half2*)ph = vh;
                *(__half2*)pl = vl;
                split2(a4[2], h0, l0);
                split2(a4[3], h1, l1);
                vh.x = h0; vh.y = h1; vl.x = l0; vl.y = l1;
                *(__half2*)(ph + 8 * c_row) = vh;
                *(__half2*)(pl + 8 * c_row) = vl;
            } else {
                const float b0 = bias[col], b1 = bias[col + 1];
                float* p = outF + (size_t)bz * c_batch + (size_t)row * c_row + col;
                *(float2*)p = make_float2(tanhf(a4[0] + b0), tanhf(a4[1] + b1));
                *(float2*)(p + 8 * c_row) = make_float2(tanhf(a4[2] + b0), tanhf(a4[3] + b1));
            }
        }
    }
}

// ---------------- conversion kernels (vectorized) ----------------
__global__ __launch_bounds__(256) void conv_q(const float* __restrict__ Q) {
    size_t i4 = ((size_t)blockIdx.x * 256 + threadIdx.x) * 4;  // over T*B*D
    float4 v = *(const float4*)(Q + i4);
    int d = (int)(i4 & (DD - 1));
    size_t j = i4 >> 10;
    int b = (int)(j & (BB - 1));
    size_t t = j >> 4;
    size_t o = ((size_t)b * TT + t) * KK2 + DD + d;
    __half h0, l0, h1, l1;
    __half2 vh, vl;
    split2(v.x, h0, l0); split2(v.y, h1, l1);
    vh.x = h0; vh.y = h1; vl.x = l0; vl.y = l1;
    *(__half2*)(g_combH + o) = vh;
    *(__half2*)(g_combL + o) = vl;
    split2(v.z, h0, l0); split2(v.w, h1, l1);
    vh.x = h0; vh.y = h1; vl.x = l0; vl.y = l1;
    *(__half2*)(g_combH + o + 2) = vh;
    *(__half2*)(g_combL + o + 2) = vl;
}

__global__ __launch_bounds__(256) void conv_c_ct(const float* __restrict__ C) {
    __shared__ float tile[32][33];
    const int b = blockIdx.z;
    const int d0 = blockIdx.x * 32, s0 = blockIdx.y * 32;
    const int tx = threadIdx.x, ty = threadIdx.y;  // (32,8)
#pragma unroll
    for (int i = 0; i < 4; i++) {
        int s = s0 + ty + i * 8;
        float v = C[((size_t)s * BB + b) * DD + d0 + tx];
        tile[ty + i * 8][tx] = v;
        __half h, l;
        split2(v, h, l);
        size_t o = ((size_t)b * SS + s) * DD + d0 + tx;
        g_cH[o] = h;
        g_cL[o] = l;
    }
    __syncthreads();
#pragma unroll
    for (int i = 0; i < 4; i++) {
        int d = d0 + ty + i * 8;
        __half h, l;
        split2(tile[tx][ty + i * 8], h, l);
        size_t o = ((size_t)b * DD + d) * SS + s0 + tx;
        g_cTH[o] = h;
        g_cTL[o] = l;
    }
}

__global__ __launch_bounds__(256) void conv_w(const float* __restrict__ W) {
    size_t i4 = ((size_t)blockIdx.x * 256 + threadIdx.x) * 4;  // over D*2D
    float4 v = *(const float4*)(W + i4);
    __half h0, l0, h1, l1;
    __half2 vh, vl;
    split2(v.x, h0, l0); split2(v.y, h1, l1);
    vh.x = h0; vh.y = h1; vl.x = l0; vl.y = l1;
    *(__half2*)(g_WH + i4) = vh;
    *(__half2*)(g_WL + i4) = vl;
    split2(v.z, h0, l0); split2(v.w, h1, l1);
    vh.x = h0; vh.y = h1; vl.x = l0; vl.y = l1;
    *(__half2*)(g_WH + i4 + 2) = vh;
    *(__half2*)(g_WL + i4 + 2) = vl;
}

// ---------------- softmax (==0 -> -inf mask), fp32 scores -> fp16 hi/lo probs ----------------
__global__ __launch_bounds__(256) void softmax_mask() {
    const size_t rowi = blockIdx.x;
    const float* p = g_scores + rowi * SS;
    __half* ph = g_PH + rowi * SS;
    __half* pl = g_PL + rowi * SS;
    const int tid = threadIdx.x;
    __shared__ float red[256];
    float v[8];
    float m = -INFINITY;
#pragma unroll
    for (int i = 0; i < 8; i++) {
        v[i] = p[tid + i * 256];
        float x = (v[i] == 0.0f) ? -INFINITY : v[i];
        m = fmaxf(m, x);
    }
    red[tid] = m;
    __syncthreads();
#pragma unroll
    for (int s = 128; s > 0; s >>= 1) {
        if (tid < s) red[tid] = fmaxf(red[tid], red[tid + s]);
        __syncthreads();
    }
    m = red[0];
    __syncthreads();
    float e[8];
    float sum = 0.0f;
#pragma unroll
    for (int i = 0; i < 8; i++) {
        e[i] = (v[i] == 0.0f) ? 0.0f : __expf(v[i] - m);
        sum += e[i];
    }
    red[tid] = sum;
    __syncthreads();
#pragma unroll
    for (int s = 128; s > 0; s >>= 1) {
        if (tid < s) red[tid] += red[tid + s];
        __syncthreads();
    }
    const float inv = 1.0f / red[0];
#pragma unroll
    for (int i = 0; i < 8; i++) {
        __half h, l;
        split2(e[i] * inv, h, l);
        ph[tid + i * 256] = h;
        pl[tid + i * 256] = l;
    }
}

// ---------------- launch ----------------
extern "C" void kernel_launch(void* const* d_in, const int* in_sizes, int n_in,
                              void* d_out, int out_size) {
    (void)in_sizes; (void)n_in; (void)out_size;
    const float* Q = (const float*)d_in[0];
    const float* C = (const float*)d_in[1];
    const float* W = (const float*)d_in[2];
    const float* bias = (const float*)d_in[3];
    float* out = (float*)d_out;

    void *pScores, *pCombH, *pCombL, *pCH, *pCL, *pCTH, *pCTL, *pPH, *pPL, *pWH, *pWL;
    cudaGetSymbolAddress(&pScores, g_scores);
    cudaGetSymbolAddress(&pCombH, g_combH);
    cudaGetSymbolAddress(&pCombL, g_combL);
    cudaGetSymbolAddress(&pCH, g_cH);
    cudaGetSymbolAddress(&pCL, g_cL);
    cudaGetSymbolAddress(&pCTH, g_cTH);
    cudaGetSymbolAddress(&pCTL, g_cTL);
    cudaGetSymbolAddress(&pPH, g_PH);
    cudaGetSymbolAddress(&pPL, g_PL);
    cudaGetSymbolAddress(&pWH, g_WH);
    cudaGetSymbolAddress(&pWL, g_WL);

    cudaFuncSetAttribute((const void*)mma_gemm<0, 3>, cudaFuncAttributeMaxDynamicSharedMemorySize, SMEM_NP3);
    cudaFuncSetAttribute((const void*)mma_gemm<1, 2>, cudaFuncAttributeMaxDynamicSharedMemorySize, SMEM_NP2);
    cudaFuncSetAttribute((const void*)mma_gemm<2, 2>, cudaFuncAttributeMaxDynamicSharedMemorySize, SMEM_NP2);

    // conversions
    conv_q<<<(unsigned)((size_t)TT * BB * DD / 1024), 256>>>(Q);
    conv_c_ct<<<dim3(DD / 32, SS / 32, BB), dim3(32, 8)>>>(C);
    conv_w<<<(unsigned)((size_t)DD * KK2 / 1024), 256>>>(W);

    // GEMM1: scores = q . c   (fused 3-term), tiles 128x256
    mma_gemm<0, 3><<<dim3(SS / 256, TT / 128, BB), 512, SMEM_NP3>>>(
        (const __half*)pCombH + DD, (const __half*)pCombL + DD,
        (size_t)KK2, (size_t)TT * KK2,
        (const __half*)pCH, (const __half*)pCL,
        (size_t)DD, (size_t)SS * DD,
        DD / 32,
        (float*)pScores, nullptr, nullptr, (size_t)SS, (size_t)TT * SS, nullptr);

    softmax_mask<<<BB * TT, 256>>>();

    // GEMM2: mix = P . cT   (fused 2-term) -> fp16 hi/lo into comb cols [0,1024)
    mma_gemm<1, 2><<<dim3(DD / 256, TT / 128, BB), 512, SMEM_NP2>>>(
        (const __half*)pPH, (const __half*)pPL,
        (size_t)SS, (size_t)TT * SS,
        (const __half*)pCTH, nullptr,
        (size_t)SS, (size_t)DD * SS,
        SS / 32,
        nullptr, (__half*)pCombH, (__half*)pCombL,
        (size_t)KK2, (size_t)TT * KK2, nullptr);

    // GEMM3: out = tanh(comb . W^T + bias)   (fused 2-term)
    mma_gemm<2, 2><<<dim3(DD / 256, TT / 128, BB), 512, SMEM_NP2>>>(
        (const __half*)pCombH, (const __half*)pCombL,
        (size_t)KK2, (size_t)TT * KK2,
        (const __half*)pWH, nullptr,
        (size_t)KK2, (size_t)0,
        KK2 / 32,
        out, nullptr, nullptr, (size_t)DD, (size_t)TT * DD, bias);
}

// round 8
// speedup vs baseline: 1.1282x; 1.1282x over previous
#include <cuda_runtime.h>
#include <cuda_fp16.h>
#include <math.h>
#include <stdint.h>

#define TT 2048
#define SS 2048
#define BB 16
#define DD 1024
#define KK2 2048

// ---------------- device scratch (static) ----------------
__device__ float  g_scores[(size_t)BB * TT * SS];   // 256 MiB
__device__ __half g_combH[(size_t)BB * TT * KK2];   // [b][t][0..1023]=mix, [1024..2047]=q
__device__ __half g_combL[(size_t)BB * TT * KK2];
__device__ __half g_cH[(size_t)BB * SS * DD];       // context hi [b][s][d]
__device__ __half g_cL[(size_t)BB * SS * DD];
__device__ __half g_cTH[(size_t)BB * DD * SS];      // context^T [b][d][s]
__device__ __half g_cTL[(size_t)BB * DD * SS];
__device__ __half g_PH[(size_t)BB * TT * SS];       // probs hi/lo
__device__ __half g_PL[(size_t)BB * TT * SS];
__device__ __half g_WH[(size_t)DD * KK2];
__device__ __half g_WL[(size_t)DD * KK2];

// ---------------- helpers ----------------
__device__ __forceinline__ void split2(float x, __half& h, __half& l) {
    h = __float2half_rn(x);
    l = __float2half_rn(x - __half2float(h));
}

__device__ __forceinline__ uint32_t smem_u32(const void* p) {
    uint32_t a;
    asm("{ .reg .u64 t; cvta.to.shared.u64 t, %1; cvt.u32.u64 %0, t; }" : "=r"(a) : "l"(p));
    return a;
}

__device__ __forceinline__ void ldsm4(uint32_t* r, uint32_t addr) {
    asm volatile("ldmatrix.sync.aligned.m8n8.x4.shared.b16 {%0,%1,%2,%3}, [%4];"
                 : "=r"(r[0]), "=r"(r[1]), "=r"(r[2]), "=r"(r[3]) : "r"(addr));
}

__device__ __forceinline__ void mma_f16(float* c, const uint32_t* a, uint32_t b0, uint32_t b1) {
    asm volatile(
        "mma.sync.aligned.m16n8k16.row.col.f32.f16.f16.f32 "
        "{%0,%1,%2,%3}, {%4,%5,%6,%7}, {%8,%9}, {%0,%1,%2,%3};"
        : "+f"(c[0]), "+f"(c[1]), "+f"(c[2]), "+f"(c[3])
        : "r"(a[0]), "r"(a[1]), "r"(a[2]), "r"(a[3]), "r"(b0), "r"(b1));
}

// KC=32: 64B logical rows, 2 rows per 128B line, validated R3/R5/R6
__device__ __forceinline__ uint32_t sw_off32(int r, int c16) {
    uint32_t line = (uint32_t)(r >> 1);
    uint32_t sub = (uint32_t)(c16 + ((r & 1) << 2));
    return (line << 7) + ((sub ^ (line & 7)) << 4);
}
// KC=64: 128B rows, 8-sub XOR swizzle, validated R4
__device__ __forceinline__ uint32_t sw_off64(int r, int c16) {
    return ((uint32_t)r << 7) + (((uint32_t)(c16 ^ (r & 7))) << 4);
}

// ---------------- fused split-precision fp16 mma.sync GEMM ----------------
// NP=3: Ah*Bh + Al*Bh + Ah*Bl      NP=2: Ah*Bh + Al*Bh
// CTA tile M128 x N128, 8 warps (4x2, warp 32x64), 2 CTAs/SM.
// KC: K-chunk (32 -> NSTG 3/4, 64 -> NSTG 2). EPI: 0=fp32, 1=fp16 hi/lo, 2=bias+tanh.
template <int EPI, int NP, int KC>
__global__ __launch_bounds__(256, 2) void mma_gemm(
    const __half* __restrict__ Ah, const __half* __restrict__ Al,
    size_t a_row, size_t a_batch,
    const __half* __restrict__ Bh, const __half* __restrict__ Bl,
    size_t b_row, size_t b_batch,
    int KCH,  // K / KC
    float* __restrict__ outF, __half* __restrict__ outH, __half* __restrict__ outL,
    size_t c_row, size_t c_batch, const float* __restrict__ bias) {
    constexpr int NT = (NP == 3) ? 4 : 3;                 // tiles per stage
    constexpr int NSTG = (NP == 3) ? 3 : ((KC == 32) ? 4 : 2);
    constexpr uint32_t TILE_B = 128 * KC * 2;             // 8KB or 16KB
    constexpr uint32_t STAGE_B = NT * TILE_B;
    constexpr uint32_t AH_OFF = 0, AL_OFF = TILE_B, BH_OFF = 2 * TILE_B, BL_OFF = 3 * TILE_B;
    constexpr int CPR = KC / 8;                           // 16B chunks per row
    constexpr int NCHUNK = 128 * CPR;
    constexpr int NK16 = KC / 16;

    extern __shared__ char smem[];
    const uint32_t sb = smem_u32(smem);
    const int tid = threadIdx.x;
    const int lane = tid & 31, wid = tid >> 5;
    const int wm = wid & 3, wn = wid >> 2;
    const int n0 = blockIdx.x * 128, m0 = blockIdx.y * 128, bz = blockIdx.z;

    const __half* A_h = Ah + (size_t)bz * a_batch + (size_t)m0 * a_row;
    const __half* A_l = Al + (size_t)bz * a_batch + (size_t)m0 * a_row;
    const __half* B_h = Bh + (size_t)bz * b_batch + (size_t)n0 * b_row;
    const __half* B_l = (NP == 3) ? (Bl + (size_t)bz * b_batch + (size_t)n0 * b_row) : nullptr;

    auto swz = [](int r, int c16) {
        return (KC == 32) ? sw_off32(r, c16) : sw_off64(r, c16);
    };

    auto load_tile = [&](uint32_t dst, const __half* g, size_t rstride, int kk) {
#pragma unroll
        for (int i = tid; i < NCHUNK; i += 256) {
            const int r = i / CPR, cc = i % CPR;
            const char* gp = (const char*)(g + (size_t)r * rstride + kk) + (cc << 4);
            asm volatile("cp.async.cg.shared.global [%0], [%1], 16;"
                         :: "r"(dst + swz(r, cc)), "l"(gp) : "memory");
        }
    };
    auto load_stage = [&](int c) {
        const int kk = c * KC;
        const uint32_t st = sb + (uint32_t)(c % NSTG) * STAGE_B;
        load_tile(st + AH_OFF, A_h, a_row, kk);
        load_tile(st + AL_OFF, A_l, a_row, kk);
        load_tile(st + BH_OFF, B_h, b_row, kk);
        if (NP == 3) load_tile(st + BL_OFF, B_l, b_row, kk);
        asm volatile("cp.async.commit_group;" ::: "memory");
    };

    // per-thread ldmatrix offsets (k16 step j via XOR j<<5)
    uint32_t offA[2], offB[4];
    {
        const int gA = lane >> 4;
#pragma unroll
        for (int mi = 0; mi < 2; mi++)
            offA[mi] = swz(wm * 32 + mi * 16 + (lane & 15), gA);
        const int gB = (lane >> 3) & 1;
        const int rb = wn * 64 + ((lane >> 4) << 3) + (lane & 7);
#pragma unroll
        for (int nj = 0; nj < 4; nj++) offB[nj] = swz(rb + nj * 16, gB);
    }

    float acc[2][8][4];
#pragma unroll
    for (int i = 0; i < 2; i++)
#pragma unroll
        for (int j = 0; j < 8; j++)
#pragma unroll
            for (int q = 0; q < 4; q++) acc[i][j][q] = 0.0f;

#pragma unroll
    for (int s = 0; s < NSTG - 1; s++) load_stage(s);

    for (int c = 0; c < KCH; c++) {
        asm volatile("cp.async.wait_group %0;" :: "n"(NSTG - 2) : "memory");
        __syncthreads();
        if (c + NSTG - 1 < KCH) load_stage(c + NSTG - 1);
        else asm volatile("cp.async.commit_group;" ::: "memory");

        const uint32_t st = sb + (uint32_t)(c % NSTG) * STAGE_B;
#pragma unroll
        for (int k16 = 0; k16 < NK16; k16++) {
            const uint32_t x = (uint32_t)(k16 << 5);
            uint32_t ah[2][4], al[2][4];
            ldsm4(ah[0], st + AH_OFF + (offA[0] ^ x));
            ldsm4(ah[1], st + AH_OFF + (offA[1] ^ x));
            ldsm4(al[0], st + AL_OFF + (offA[0] ^ x));
            ldsm4(al[1], st + AL_OFF + (offA[1] ^ x));
#pragma unroll
            for (int nj = 0; nj < 4; nj++) {
                uint32_t bh[4];
                ldsm4(bh, st + BH_OFF + (offB[nj] ^ x));
                mma_f16(acc[0][2 * nj], ah[0], bh[0], bh[1]);
                mma_f16(acc[0][2 * nj + 1], ah[0], bh[2], bh[3]);
                mma_f16(acc[1][2 * nj], ah[1], bh[0], bh[1]);
                mma_f16(acc[1][2 * nj + 1], ah[1], bh[2], bh[3]);
                mma_f16(acc[0][2 * nj], al[0], bh[0], bh[1]);
                mma_f16(acc[0][2 * nj + 1], al[0], bh[2], bh[3]);
                mma_f16(acc[1][2 * nj], al[1], bh[0], bh[1]);
                mma_f16(acc[1][2 * nj + 1], al[1], bh[2], bh[3]);
                if (NP == 3) {
                    uint32_t bl[4];
                    ldsm4(bl, st + BL_OFF + (offB[nj] ^ x));
                    mma_f16(acc[0][2 * nj], ah[0], bl[0], bl[1]);
                    mma_f16(acc[0][2 * nj + 1], ah[0], bl[2], bl[3]);
                    mma_f16(acc[1][2 * nj], ah[1], bl[0], bl[1]);
                    mma_f16(acc[1][2 * nj + 1], ah[1], bl[2], bl[3]);
                }
            }
        }
    }

    // -------- epilogue --------
    const int trow = lane >> 2, tcol = (lane & 3) * 2;
#pragma unroll
    for (int mi = 0; mi < 2; mi++) {
#pragma unroll
        for (int nj = 0; nj < 8; nj++) {
            const int row = m0 + wm * 32 + mi * 16 + trow;
            const int col = n0 + wn * 64 + nj * 8 + tcol;
            const float* a4 = acc[mi][nj];
            if (EPI == 0) {
                float* p = outF + (size_t)bz * c_batch + (size_t)row * c_row + col;
                *(float2*)p = make_float2(a4[0], a4[1]);
                *(float2*)(p + 8 * c_row) = make_float2(a4[2], a4[3]);
            } else if (EPI == 1) {
                __half* ph = outH + (size_t)bz * c_batch + (size_t)row * c_row + col;
                __half* pl = outL + (size_t)bz * c_batch + (size_t)row * c_row + col;
                __half h0, l0, h1, l1;
                split2(a4[0], h0, l0);
                split2(a4[1], h1, l1);
                __half2 vh, vl;
                vh.x = h0; vh.y = h1; vl.x = l0; vl.y = l1;
                *(__half2*)ph = vh;
                *(__half2*)pl = vl;
                split2(a4[2], h0, l0);
                split2(a4[3], h1, l1);
                vh.x = h0; vh.y = h1; vl.x = l0; vl.y = l1;
                *(__half2*)(ph + 8 * c_row) = vh;
                *(__half2*)(pl + 8 * c_row) = vl;
            } else {
                const float b0 = bias[col], b1 = bias[col + 1];
                float* p = outF + (size_t)bz * c_batch + (size_t)row * c_row + col;
                *(float2*)p = make_float2(tanhf(a4[0] + b0), tanhf(a4[1] + b1));
                *(float2*)(p + 8 * c_row) = make_float2(tanhf(a4[2] + b0), tanhf(a4[3] + b1));
            }
        }
    }
}

// ---------------- conversion kernels (vectorized) ----------------
__global__ __launch_bounds__(256) void conv_q(const float* __restrict__ Q) {
    size_t i4 = ((size_t)blockIdx.x * 256 + threadIdx.x) * 4;  // over T*B*D
    float4 v = *(const float4*)(Q + i4);
    int d = (int)(i4 & (DD - 1));
    size_t j = i4 >> 10;
    int b = (int)(j & (BB - 1));
    size_t t = j >> 4;
    size_t o = ((size_t)b * TT + t) * KK2 + DD + d;
    __half h0, l0, h1, l1;
    __half2 vh, vl;
    split2(v.x, h0, l0); split2(v.y, h1, l1);
    vh.x = h0; vh.y = h1; vl.x = l0; vl.y = l1;
    *(__half2*)(g_combH + o) = vh;
    *(__half2*)(g_combL + o) = vl;
    split2(v.z, h0, l0); split2(v.w, h1, l1);
    vh.x = h0; vh.y = h1; vl.x = l0; vl.y = l1;
    *(__half2*)(g_combH + o + 2) = vh;
    *(__half2*)(g_combL + o + 2) = vl;
}

__global__ __launch_bounds__(256) void conv_c_ct(const float* __restrict__ C) {
    __shared__ float tile[32][33];
    const int b = blockIdx.z;
    const int d0 = blockIdx.x * 32, s0 = blockIdx.y * 32;
    const int tx = threadIdx.x, ty = threadIdx.y;  // (32,8)
#pragma unroll
    for (int i = 0; i < 4; i++) {
        int s = s0 + ty + i * 8;
        float v = C[((size_t)s * BB + b) * DD + d0 + tx];
        tile[ty + i * 8][tx] = v;
        __half h, l;
        split2(v, h, l);
        size_t o = ((size_t)b * SS + s) * DD + d0 + tx;
        g_cH[o] = h;
        g_cL[o] = l;
    }
    __syncthreads();
#pragma unroll
    for (int i = 0; i < 4; i++) {
        int d = d0 + ty + i * 8;
        __half h, l;
        split2(tile[tx][ty + i * 8], h, l);
        size_t o = ((size_t)b * DD + d) * SS + s0 + tx;
        g_cTH[o] = h;
        g_cTL[o] = l;
    }
}

__global__ __launch_bounds__(256) void conv_w(const float* __restrict__ W) {
    size_t i4 = ((size_t)blockIdx.x * 256 + threadIdx.x) * 4;  // over D*2D
    float4 v = *(const float4*)(W + i4);
    __half h0, l0, h1, l1;
    __half2 vh, vl;
    split2(v.x, h0, l0); split2(v.y, h1, l1);
    vh.x = h0; vh.y = h1; vl.x = l0; vl.y = l1;
    *(__half2*)(g_WH + i4) = vh;
    *(__half2*)(g_WL + i4) = vl;
    split2(v.z, h0, l0); split2(v.w, h1, l1);
    vh.x = h0; vh.y = h1; vl.x = l0; vl.y = l1;
    *(__half2*)(g_WH + i4 + 2) = vh;
    *(__half2*)(g_WL + i4 + 2) = vl;
}

// ---------------- softmax (==0 -> -inf mask), fp32 scores -> fp16 hi/lo probs ----------------
__global__ __launch_bounds__(256) void softmax_mask() {
    const size_t rowi = blockIdx.x;
    const float4* p4 = (const float4*)(g_scores + rowi * SS);
    __half2* ph2 = (__half2*)(g_PH + rowi * SS);
    __half2* pl2 = (__half2*)(g_PL + rowi * SS);
    const int tid = threadIdx.x;
    __shared__ float red[256];
    float4 v[2];
    float m = -INFINITY;
#pragma unroll
    for (int i = 0; i < 2; i++) {
        v[i] = p4[tid + i * 256];
        float* f = (float*)&v[i];
#pragma unroll
        for (int q = 0; q < 4; q++) {
            float x = (f[q] == 0.0f) ? -INFINITY : f[q];
            m = fmaxf(m, x);
        }
    }
    red[tid] = m;
    __syncthreads();
#pragma unroll
    for (int s = 128; s > 0; s >>= 1) {
        if (tid < s) red[tid] = fmaxf(red[tid], red[tid + s]);
        __syncthreads();
    }
    m = red[0];
    __syncthreads();
    float e[8];
    float sum = 0.0f;
#pragma unroll
    for (int i = 0; i < 2; i++) {
        float* f = (float*)&v[i];
#pragma unroll
        for (int q = 0; q < 4; q++) {
            float x = (f[q] == 0.0f) ? 0.0f : __expf(f[q] - m);
            e[i * 4 + q] = x;
            sum += x;
        }
    }
    red[tid] = sum;
    __syncthreads();
#pragma unroll
    for (int s = 128; s > 0; s >>= 1) {
        if (tid < s) red[tid] += red[tid + s];
        __syncthreads();
    }
    const float inv = 1.0f / red[0];
#pragma unroll
    for (int i = 0; i < 2; i++) {
#pragma unroll
        for (int q = 0; q < 2; q++) {
            __half h0, l0, h1, l1;
            split2(e[i * 4 + q * 2] * inv, h0, l0);
            split2(e[i * 4 + q * 2 + 1] * inv, h1, l1);
            __half2 vh, vl;
            vh.x = h0; vh.y = h1; vl.x = l0; vl.y = l1;
            ph2[(tid + i * 256) * 2 + q] = vh;
            pl2[(tid + i * 256) * 2 + q] = vl;
        }
    }
}

// ---------------- launch ----------------
#define SMEM_G1 98304   // NP3 KC32: 3 stages x 32KB
#define SMEM_G23 98304  // NP2 KC64: 2 stages x 48KB

extern "C" void kernel_launch(void* const* d_in, const int* in_sizes, int n_in,
                              void* d_out, int out_size) {
    (void)in_sizes; (void)n_in; (void)out_size;
    const float* Q = (const float*)d_in[0];
    const float* C = (const float*)d_in[1];
    const float* W = (const float*)d_in[2];
    const float* bias = (const float*)d_in[3];
    float* out = (float*)d_out;

    void *pScores, *pCombH, *pCombL, *pCH, *pCL, *pCTH, *pCTL, *pPH, *pPL, *pWH, *pWL;
    cudaGetSymbolAddress(&pScores, g_scores);
    cudaGetSymbolAddress(&pCombH, g_combH);
    cudaGetSymbolAddress(&pCombL, g_combL);
    cudaGetSymbolAddress(&pCH, g_cH);
    cudaGetSymbolAddress(&pCL, g_cL);
    cudaGetSymbolAddress(&pCTH, g_cTH);
    cudaGetSymbolAddress(&pCTL, g_cTL);
    cudaGetSymbolAddress(&pPH, g_PH);
    cudaGetSymbolAddress(&pPL, g_PL);
    cudaGetSymbolAddress(&pWH, g_WH);
    cudaGetSymbolAddress(&pWL, g_WL);

    cudaFuncSetAttribute((const void*)mma_gemm<0, 3, 32>, cudaFuncAttributeMaxDynamicSharedMemorySize, SMEM_G1);
    cudaFuncSetAttribute((const void*)mma_gemm<1, 2, 64>, cudaFuncAttributeMaxDynamicSharedMemorySize, SMEM_G23);
    cudaFuncSetAttribute((const void*)mma_gemm<2, 2, 64>, cudaFuncAttributeMaxDynamicSharedMemorySize, SMEM_G23);

    // conversions
    conv_q<<<(unsigned)((size_t)TT * BB * DD / 1024), 256>>>(Q);
    conv_c_ct<<<dim3(DD / 32, SS / 32, BB), dim3(32, 8)>>>(C);
    conv_w<<<(unsigned)((size_t)DD * KK2 / 1024), 256>>>(W);

    // GEMM1: scores = q . c   (fused 3-term, KC32/NSTG3 — R6 config)
    mma_gemm<0, 3, 32><<<dim3(SS / 128, TT / 128, BB), 256, SMEM_G1>>>(
        (const __half*)pCombH + DD, (const __half*)pCombL + DD,
        (size_t)KK2, (size_t)TT * KK2,
        (const __half*)pCH, (const __half*)pCL,
        (size_t)DD, (size_t)SS * DD,
        DD / 32,
        (float*)pScores, nullptr, nullptr, (size_t)SS, (size_t)TT * SS, nullptr);

    softmax_mask<<<BB * TT, 256>>>();

    // GEMM2: mix = P . cT   (fused 2-term, KC64/NSTG2) -> fp16 hi/lo into comb cols [0,1024)
    mma_gemm<1, 2, 64><<<dim3(DD / 128, TT / 128, BB), 256, SMEM_G23>>>(
        (const __half*)pPH, (const __half*)pPL,
        (size_t)SS, (size_t)TT * SS,
        (const __half*)pCTH, nullptr,
        (size_t)SS, (size_t)DD * SS,
        SS / 64,
        nullptr, (__half*)pCombH, (__half*)pCombL,
        (size_t)KK2, (size_t)TT * KK2, nullptr);

    // GEMM3: out = tanh(comb . W^T + bias)   (fused 2-term, KC64/NSTG2)
    mma_gemm<2, 2, 64><<<dim3(DD / 128, TT / 128, BB), 256, SMEM_G23>>>(
        (const __half*)pCombH, (const __half*)pCombL,
        (size_t)KK2, (size_t)TT * KK2,
        (const __half*)pWH, nullptr,
        (size_t)KK2, (size_t)0,
        KK2 / 64,
        out, nullptr, nullptr, (size_t)DD, (size_t)TT * DD, bias);
}

// round 9
// speedup vs baseline: 1.4470x; 1.2827x over previous
#include <cuda_runtime.h>
#include <cuda_fp16.h>
#include <math.h>
#include <stdint.h>

#define TT 2048
#define SS 2048
#define BB 16
#define DD 1024
#define KK2 2048

// ---------------- device scratch (static) ----------------
__device__ float  g_scores[(size_t)BB * TT * SS];   // 256 MiB
__device__ __half g_combH[(size_t)BB * TT * KK2];   // [b][t][0..1023]=mix, [1024..2047]=q
__device__ __half g_combL[(size_t)BB * TT * KK2];   // lo: only q-half used (GEMM1 A)
__device__ __half g_cH[(size_t)BB * SS * DD];       // context hi [b][s][d]
__device__ __half g_cL[(size_t)BB * SS * DD];       // context lo (GEMM1 B)
__device__ __half g_cTH[(size_t)BB * DD * SS];      // context^T hi [b][d][s]
__device__ __half g_PH[(size_t)BB * TT * SS];       // probs hi
__device__ __half g_WH[(size_t)DD * KK2];

// ---------------- helpers ----------------
__device__ __forceinline__ void split2(float x, __half& h, __half& l) {
    h = __float2half_rn(x);
    l = __float2half_rn(x - __half2float(h));
}

__device__ __forceinline__ uint32_t smem_u32(const void* p) {
    uint32_t a;
    asm("{ .reg .u64 t; cvta.to.shared.u64 t, %1; cvt.u32.u64 %0, t; }" : "=r"(a) : "l"(p));
    return a;
}

__device__ __forceinline__ void ldsm4(uint32_t* r, uint32_t addr) {
    asm volatile("ldmatrix.sync.aligned.m8n8.x4.shared.b16 {%0,%1,%2,%3}, [%4];"
                 : "=r"(r[0]), "=r"(r[1]), "=r"(r[2]), "=r"(r[3]) : "r"(addr));
}

__device__ __forceinline__ void mma_f16(float* c, const uint32_t* a, uint32_t b0, uint32_t b1) {
    asm volatile(
        "mma.sync.aligned.m16n8k16.row.col.f32.f16.f16.f32 "
        "{%0,%1,%2,%3}, {%4,%5,%6,%7}, {%8,%9}, {%0,%1,%2,%3};"
        : "+f"(c[0]), "+f"(c[1]), "+f"(c[2]), "+f"(c[3])
        : "r"(a[0]), "r"(a[1]), "r"(a[2]), "r"(a[3]), "r"(b0), "r"(b1));
}

// KC=32: 64B logical rows, 2 rows per 128B line (validated R3/R5/R6/R8)
__device__ __forceinline__ uint32_t sw_off32(int r, int c16) {
    uint32_t line = (uint32_t)(r >> 1);
    uint32_t sub = (uint32_t)(c16 + ((r & 1) << 2));
    return (line << 7) + ((sub ^ (line & 7)) << 4);
}
// KC=64: 128B rows, 8-sub XOR swizzle (validated R4/R8)
__device__ __forceinline__ uint32_t sw_off64(int r, int c16) {
    return ((uint32_t)r << 7) + (((uint32_t)(c16 ^ (r & 7))) << 4);
}

// ---------------- fused split-precision fp16 mma.sync GEMM ----------------
// NP=3: Ah*Bh + Al*Bh + Ah*Bl    NP=2: Ah*Bh + Al*Bh    NP=1: Ah*Bh
// CTA tile M128 x N128, 8 warps (4x2, warp 32x64), 2 CTAs/SM.
// EPI: 0=fp32 store, 1=fp16 hi store, 2=bias+tanh fp32.
template <int EPI, int NP, int KC>
__global__ __launch_bounds__(256, 2) void mma_gemm(
    const __half* __restrict__ Ah, const __half* __restrict__ Al,
    size_t a_row, size_t a_batch,
    const __half* __restrict__ Bh, const __half* __restrict__ Bl,
    size_t b_row, size_t b_batch,
    int KCH,  // K / KC
    float* __restrict__ outF, __half* __restrict__ outH,
    size_t c_row, size_t c_batch, const float* __restrict__ bias) {
    constexpr int NT = (NP == 3) ? 4 : ((NP == 2) ? 3 : 2);  // tiles per stage
    constexpr int NSTG = (NP == 3) ? 3 : ((NP == 2) ? ((KC == 32) ? 4 : 2) : 3);
    constexpr uint32_t TILE_B = 128 * KC * 2;                // 8KB or 16KB
    constexpr uint32_t STAGE_B = NT * TILE_B;
    constexpr uint32_t AH_OFF = 0;
    constexpr uint32_t AL_OFF = (NP >= 2) ? TILE_B : 0;
    constexpr uint32_t BH_OFF = (NP >= 2) ? 2 * TILE_B : TILE_B;
    constexpr uint32_t BL_OFF = 3 * TILE_B;
    constexpr int CPR = KC / 8;  // 16B chunks per row
    constexpr int NCHUNK = 128 * CPR;
    constexpr int NK16 = KC / 16;

    extern __shared__ char smem[];
    const uint32_t sb = smem_u32(smem);
    const int tid = threadIdx.x;
    const int lane = tid & 31, wid = tid >> 5;
    const int wm = wid & 3, wn = wid >> 2;
    const int n0 = blockIdx.x * 128, m0 = blockIdx.y * 128, bz = blockIdx.z;

    const __half* A_h = Ah + (size_t)bz * a_batch + (size_t)m0 * a_row;
    const __half* A_l = (NP >= 2) ? (Al + (size_t)bz * a_batch + (size_t)m0 * a_row) : nullptr;
    const __half* B_h = Bh + (size_t)bz * b_batch + (size_t)n0 * b_row;
    const __half* B_l = (NP == 3) ? (Bl + (size_t)bz * b_batch + (size_t)n0 * b_row) : nullptr;

    auto swz = [](int r, int c16) {
        return (KC == 32) ? sw_off32(r, c16) : sw_off64(r, c16);
    };

    auto load_tile = [&](uint32_t dst, const __half* g, size_t rstride, int kk) {
#pragma unroll
        for (int i = tid; i < NCHUNK; i += 256) {
            const int r = i / CPR, cc = i % CPR;
            const char* gp = (const char*)(g + (size_t)r * rstride + kk) + (cc << 4);
            asm volatile("cp.async.cg.shared.global [%0], [%1], 16;"
                         :: "r"(dst + swz(r, cc)), "l"(gp) : "memory");
        }
    };
    auto load_stage = [&](int c) {
        const int kk = c * KC;
        const uint32_t st = sb + (uint32_t)(c % NSTG) * STAGE_B;
        load_tile(st + AH_OFF, A_h, a_row, kk);
        if (NP >= 2) load_tile(st + AL_OFF, A_l, a_row, kk);
        load_tile(st + BH_OFF, B_h, b_row, kk);
        if (NP == 3) load_tile(st + BL_OFF, B_l, b_row, kk);
        asm volatile("cp.async.commit_group;" ::: "memory");
    };

    // per-thread ldmatrix offsets (k16 step j via XOR j<<5)
    uint32_t offA[2], offB[4];
    {
        const int gA = lane >> 4;
#pragma unroll
        for (int mi = 0; mi < 2; mi++)
            offA[mi] = swz(wm * 32 + mi * 16 + (lane & 15), gA);
        const int gB = (lane >> 3) & 1;
        const int rb = wn * 64 + ((lane >> 4) << 3) + (lane & 7);
#pragma unroll
        for (int nj = 0; nj < 4; nj++) offB[nj] = swz(rb + nj * 16, gB);
    }

    float acc[2][8][4];
#pragma unroll
    for (int i = 0; i < 2; i++)
#pragma unroll
        for (int j = 0; j < 8; j++)
#pragma unroll
            for (int q = 0; q < 4; q++) acc[i][j][q] = 0.0f;

#pragma unroll
    for (int s = 0; s < NSTG - 1; s++) load_stage(s);

    for (int c = 0; c < KCH; c++) {
        asm volatile("cp.async.wait_group %0;" :: "n"(NSTG - 2) : "memory");
        __syncthreads();
        if (c + NSTG - 1 < KCH) load_stage(c + NSTG - 1);
        else asm volatile("cp.async.commit_group;" ::: "memory");

        const uint32_t st = sb + (uint32_t)(c % NSTG) * STAGE_B;
#pragma unroll
        for (int k16 = 0; k16 < NK16; k16++) {
            const uint32_t x = (uint32_t)(k16 << 5);
            uint32_t ah[2][4], al[2][4];
            ldsm4(ah[0], st + AH_OFF + (offA[0] ^ x));
            ldsm4(ah[1], st + AH_OFF + (offA[1] ^ x));
            if (NP >= 2) {
                ldsm4(al[0], st + AL_OFF + (offA[0] ^ x));
                ldsm4(al[1], st + AL_OFF + (offA[1] ^ x));
            }
#pragma unroll
            for (int nj = 0; nj < 4; nj++) {
                uint32_t bh[4];
                ldsm4(bh, st + BH_OFF + (offB[nj] ^ x));
                mma_f16(acc[0][2 * nj], ah[0], bh[0], bh[1]);
                mma_f16(acc[0][2 * nj + 1], ah[0], bh[2], bh[3]);
                mma_f16(acc[1][2 * nj], ah[1], bh[0], bh[1]);
                mma_f16(acc[1][2 * nj + 1], ah[1], bh[2], bh[3]);
                if (NP >= 2) {
                    mma_f16(acc[0][2 * nj], al[0], bh[0], bh[1]);
                    mma_f16(acc[0][2 * nj + 1], al[0], bh[2], bh[3]);
                    mma_f16(acc[1][2 * nj], al[1], bh[0], bh[1]);
                    mma_f16(acc[1][2 * nj + 1], al[1], bh[2], bh[3]);
                }
                if (NP == 3) {
                    uint32_t bl[4];
                    ldsm4(bl, st + BL_OFF + (offB[nj] ^ x));
                    mma_f16(acc[0][2 * nj], ah[0], bl[0], bl[1]);
                    mma_f16(acc[0][2 * nj + 1], ah[0], bl[2], bl[3]);
                    mma_f16(acc[1][2 * nj], ah[1], bl[0], bl[1]);
                    mma_f16(acc[1][2 * nj + 1], ah[1], bl[2], bl[3]);
                }
            }
        }
    }

    // -------- epilogue --------
    const int trow = lane >> 2, tcol = (lane & 3) * 2;
#pragma unroll
    for (int mi = 0; mi < 2; mi++) {
#pragma unroll
        for (int nj = 0; nj < 8; nj++) {
            const int row = m0 + wm * 32 + mi * 16 + trow;
            const int col = n0 + wn * 64 + nj * 8 + tcol;
            const float* a4 = acc[mi][nj];
            if (EPI == 0) {
                float* p = outF + (size_t)bz * c_batch + (size_t)row * c_row + col;
                *(float2*)p = make_float2(a4[0], a4[1]);
                *(float2*)(p + 8 * c_row) = make_float2(a4[2], a4[3]);
            } else if (EPI == 1) {
                __half* ph = outH + (size_t)bz * c_batch + (size_t)row * c_row + col;
                __half2 vh;
                vh.x = __float2half_rn(a4[0]);
                vh.y = __float2half_rn(a4[1]);
                *(__half2*)ph = vh;
                vh.x = __float2half_rn(a4[2]);
                vh.y = __float2half_rn(a4[3]);
                *(__half2*)(ph + 8 * c_row) = vh;
            } else {
                const float b0 = bias[col], b1 = bias[col + 1];
                float* p = outF + (size_t)bz * c_batch + (size_t)row * c_row + col;
                *(float2*)p = make_float2(tanhf(a4[0] + b0), tanhf(a4[1] + b1));
                *(float2*)(p + 8 * c_row) = make_float2(tanhf(a4[2] + b0), tanhf(a4[3] + b1));
            }
        }
    }
}

// ---------------- conversion kernels (vectorized) ----------------
__global__ __launch_bounds__(256) void conv_q(const float* __restrict__ Q) {
    size_t i4 = ((size_t)blockIdx.x * 256 + threadIdx.x) * 4;  // over T*B*D
    float4 v = *(const float4*)(Q + i4);
    int d = (int)(i4 & (DD - 1));
    size_t j = i4 >> 10;
    int b = (int)(j & (BB - 1));
    size_t t = j >> 4;
    size_t o = ((size_t)b * TT + t) * KK2 + DD + d;
    __half h0, l0, h1, l1;
    __half2 vh, vl;
    split2(v.x, h0, l0); split2(v.y, h1, l1);
    vh.x = h0; vh.y = h1; vl.x = l0; vl.y = l1;
    *(__half2*)(g_combH + o) = vh;
    *(__half2*)(g_combL + o) = vl;
    split2(v.z, h0, l0); split2(v.w, h1, l1);
    vh.x = h0; vh.y = h1; vl.x = l0; vl.y = l1;
    *(__half2*)(g_combH + o + 2) = vh;
    *(__half2*)(g_combL + o + 2) = vl;
}

__global__ __launch_bounds__(256) void conv_c_ct(const float* __restrict__ C) {
    __shared__ float tile[32][33];
    const int b = blockIdx.z;
    const int d0 = blockIdx.x * 32, s0 = blockIdx.y * 32;
    const int tx = threadIdx.x, ty = threadIdx.y;  // (32,8)
#pragma unroll
    for (int i = 0; i < 4; i++) {
        int s = s0 + ty + i * 8;
        float v = C[((size_t)s * BB + b) * DD + d0 + tx];
        tile[ty + i * 8][tx] = v;
        __half h, l;
        split2(v, h, l);
        size_t o = ((size_t)b * SS + s) * DD + d0 + tx;
        g_cH[o] = h;
        g_cL[o] = l;
    }
    __syncthreads();
#pragma unroll
    for (int i = 0; i < 4; i++) {
        int d = d0 + ty + i * 8;
        size_t o = ((size_t)b * DD + d) * SS + s0 + tx;
        g_cTH[o] = __float2half_rn(tile[tx][ty + i * 8]);
    }
}

__global__ __launch_bounds__(256) void conv_w(const float* __restrict__ W) {
    size_t i4 = ((size_t)blockIdx.x * 256 + threadIdx.x) * 4;  // over D*2D
    float4 v = *(const float4*)(W + i4);
    __half2 vh;
    vh.x = __float2half_rn(v.x);
    vh.y = __float2half_rn(v.y);
    *(__half2*)(g_WH + i4) = vh;
    vh.x = __float2half_rn(v.z);
    vh.y = __float2half_rn(v.w);
    *(__half2*)(g_WH + i4 + 2) = vh;
}

// ---------------- softmax (==0 -> -inf mask), fp32 scores -> fp16 probs ----------------
__global__ __launch_bounds__(256) void softmax_mask() {
    const size_t rowi = blockIdx.x;
    const float4* p4 = (const float4*)(g_scores + rowi * SS);
    __half2* ph2 = (__half2*)(g_PH + rowi * SS);
    const int tid = threadIdx.x;
    __shared__ float red[256];
    float4 v[2];
    float m = -INFINITY;
#pragma unroll
    for (int i = 0; i < 2; i++) {
        v[i] = p4[tid + i * 256];
        float* f = (float*)&v[i];
#pragma unroll
        for (int q = 0; q < 4; q++) {
            float x = (f[q] == 0.0f) ? -INFINITY : f[q];
            m = fmaxf(m, x);
        }
    }
    red[tid] = m;
    __syncthreads();
#pragma unroll
    for (int s = 128; s > 0; s >>= 1) {
        if (tid < s) red[tid] = fmaxf(red[tid], red[tid + s]);
        __syncthreads();
    }
    m = red[0];
    __syncthreads();
    float e[8];
    float sum = 0.0f;
#pragma unroll
    for (int i = 0; i < 2; i++) {
        float* f = (float*)&v[i];
#pragma unroll
        for (int q = 0; q < 4; q++) {
            float x = (f[q] == 0.0f) ? 0.0f : __expf(f[q] - m);
            e[i * 4 + q] = x;
            sum += x;
        }
    }
    red[tid] = sum;
    __syncthreads();
#pragma unroll
    for (int s = 128; s > 0; s >>= 1) {
        if (tid < s) red[tid] += red[tid + s];
        __syncthreads();
    }
    const float inv = 1.0f / red[0];
#pragma unroll
    for (int i = 0; i < 2; i++) {
#pragma unroll
        for (int q = 0; q < 2; q++) {
            __half2 vh;
            vh.x = __float2half_rn(e[i * 4 + q * 2] * inv);
            vh.y = __float2half_rn(e[i * 4 + q * 2 + 1] * inv);
            ph2[(tid + i * 256) * 2 + q] = vh;
        }
    }
}

// ---------------- launch ----------------
#define SMEM_G1 98304   // NP3 KC32: 3 stages x 32KB
#define SMEM_G23 98304  // NP1 KC64: 3 stages x 32KB

extern "C" void kernel_launch(void* const* d_in, const int* in_sizes, int n_in,
                              void* d_out, int out_size) {
    (void)in_sizes; (void)n_in; (void)out_size;
    const float* Q = (const float*)d_in[0];
    const float* C = (const float*)d_in[1];
    const float* W = (const float*)d_in[2];
    const float* bias = (const float*)d_in[3];
    float* out = (float*)d_out;

    void *pScores, *pCombH, *pCombL, *pCH, *pCL, *pCTH, *pPH, *pWH;
    cudaGetSymbolAddress(&pScores, g_scores);
    cudaGetSymbolAddress(&pCombH, g_combH);
    cudaGetSymbolAddress(&pCombL, g_combL);
    cudaGetSymbolAddress(&pCH, g_cH);
    cudaGetSymbolAddress(&pCL, g_cL);
    cudaGetSymbolAddress(&pCTH, g_cTH);
    cudaGetSymbolAddress(&pPH, g_PH);
    cudaGetSymbolAddress(&pWH, g_WH);

    cudaFuncSetAttribute((const void*)mma_gemm<0, 3, 32>, cudaFuncAttributeMaxDynamicSharedMemorySize, SMEM_G1);
    cudaFuncSetAttribute((const void*)mma_gemm<1, 1, 64>, cudaFuncAttributeMaxDynamicSharedMemorySize, SMEM_G23);
    cudaFuncSetAttribute((const void*)mma_gemm<2, 1, 64>, cudaFuncAttributeMaxDynamicSharedMemorySize, SMEM_G23);

    // conversions
    conv_q<<<(unsigned)((size_t)TT * BB * DD / 1024), 256>>>(Q);
    conv_c_ct<<<dim3(DD / 32, SS / 32, BB), dim3(32, 8)>>>(C);
    conv_w<<<(unsigned)((size_t)DD * KK2 / 1024), 256>>>(W);

    // GEMM1: scores = q . c   (fused 3-term, KC32/NSTG3)
    mma_gemm<0, 3, 32><<<dim3(SS / 128, TT / 128, BB), 256, SMEM_G1>>>(
        (const __half*)pCombH + DD, (const __half*)pCombL + DD,
        (size_t)KK2, (size_t)TT * KK2,
        (const __half*)pCH, (const __half*)pCL,
        (size_t)DD, (size_t)SS * DD,
        DD / 32,
        (float*)pScores, nullptr, (size_t)SS, (size_t)TT * SS, nullptr);

    softmax_mask<<<BB * TT, 256>>>();

    // GEMM2: mix = P . cT   (1-pass fp16, KC64/NSTG3) -> fp16 into comb cols [0,1024)
    mma_gemm<1, 1, 64><<<dim3(DD / 128, TT / 128, BB), 256, SMEM_G23>>>(
        (const __half*)pPH, nullptr,
        (size_t)SS, (size_t)TT * SS,
        (const __half*)pCTH, nullptr,
        (size_t)SS, (size_t)DD * SS,
        SS / 64,
        nullptr, (__half*)pCombH, (size_t)KK2, (size_t)TT * KK2, nullptr);

    // GEMM3: out = tanh(comb . W^T + bias)   (1-pass fp16, KC64/NSTG3)
    mma_gemm<2, 1, 64><<<dim3(DD / 128, TT / 128, BB), 256, SMEM_G23>>>(
        (const __half*)pCombH, nullptr,
        (size_t)KK2, (size_t)TT * KK2,
        (const __half*)pWH, nullptr,
        (size_t)KK2, (size_t)0,
        KK2 / 64,
        out, nullptr, (size_t)DD, (size_t)TT * DD, bias);
}

// round 10
// speedup vs baseline: 1.8009x; 1.2445x over previous
#include <cuda_runtime.h>
#include <cuda_fp16.h>
#include <math.h>
#include <stdint.h>

#define TT 2048
#define SS 2048
#define BB 16
#define DD 1024
#define KK2 2048

// ---------------- device scratch (static) ----------------
__device__ float  g_scores[(size_t)BB * TT * SS];   // 256 MiB
__device__ __half g_combH[(size_t)BB * TT * KK2];   // [b][t][0..1023]=mix, [1024..2047]=q
__device__ __half g_combL[(size_t)BB * TT * KK2];   // lo: only q-half used (GEMM1 A)
__device__ __half g_cH[(size_t)BB * SS * DD];       // context hi [b][s][d]
__device__ __half g_cTH[(size_t)BB * DD * SS];      // context^T hi [b][d][s]
__device__ __half g_PH[(size_t)BB * TT * SS];       // probs hi
__device__ __half g_WH[(size_t)DD * KK2];

// ---------------- helpers ----------------
__device__ __forceinline__ void split2(float x, __half& h, __half& l) {
    h = __float2half_rn(x);
    l = __float2half_rn(x - __half2float(h));
}

__device__ __forceinline__ uint32_t smem_u32(const void* p) {
    uint32_t a;
    asm("{ .reg .u64 t; cvta.to.shared.u64 t, %1; cvt.u32.u64 %0, t; }" : "=r"(a) : "l"(p));
    return a;
}

__device__ __forceinline__ void ldsm4(uint32_t* r, uint32_t addr) {
    asm volatile("ldmatrix.sync.aligned.m8n8.x4.shared.b16 {%0,%1,%2,%3}, [%4];"
                 : "=r"(r[0]), "=r"(r[1]), "=r"(r[2]), "=r"(r[3]) : "r"(addr));
}

__device__ __forceinline__ void mma_f16(float* c, const uint32_t* a, uint32_t b0, uint32_t b1) {
    asm volatile(
        "mma.sync.aligned.m16n8k16.row.col.f32.f16.f16.f32 "
        "{%0,%1,%2,%3}, {%4,%5,%6,%7}, {%8,%9}, {%0,%1,%2,%3};"
        : "+f"(c[0]), "+f"(c[1]), "+f"(c[2]), "+f"(c[3])
        : "r"(a[0]), "r"(a[1]), "r"(a[2]), "r"(a[3]), "r"(b0), "r"(b1));
}

// KC=32: 64B logical rows, 2 rows per 128B line (validated R3/R5/R6/R8)
__device__ __forceinline__ uint32_t sw_off32(int r, int c16) {
    uint32_t line = (uint32_t)(r >> 1);
    uint32_t sub = (uint32_t)(c16 + ((r & 1) << 2));
    return (line << 7) + ((sub ^ (line & 7)) << 4);
}
// KC=64: 128B rows, 8-sub XOR swizzle (validated R4/R8/R9)
__device__ __forceinline__ uint32_t sw_off64(int r, int c16) {
    return ((uint32_t)r << 7) + (((uint32_t)(c16 ^ (r & 7))) << 4);
}

// ---------------- fused split-precision fp16 mma.sync GEMM ----------------
// NP=3: Ah*Bh + Al*Bh + Ah*Bl    NP=2: Ah*Bh + Al*Bh    NP=1: Ah*Bh
// CTA tile M128 x N128, 8 warps (4x2, warp 32x64), 2 CTAs/SM.
// EPI: 0=fp32 store, 1=fp16 hi store, 2=bias+tanh fp32.
template <int EPI, int NP, int KC>
__global__ __launch_bounds__(256, 2) void mma_gemm(
    const __half* __restrict__ Ah, const __half* __restrict__ Al,
    size_t a_row, size_t a_batch,
    const __half* __restrict__ Bh, const __half* __restrict__ Bl,
    size_t b_row, size_t b_batch,
    int KCH,  // K / KC
    float* __restrict__ outF, __half* __restrict__ outH,
    size_t c_row, size_t c_batch, const float* __restrict__ bias) {
    constexpr int NT = (NP == 3) ? 4 : ((NP == 2) ? 3 : 2);  // tiles per stage
    constexpr int NSTG = (NP == 3) ? 3 : ((NP == 2) ? ((KC == 32) ? 4 : 2) : 3);
    constexpr uint32_t TILE_B = 128 * KC * 2;                // 8KB or 16KB
    constexpr uint32_t STAGE_B = NT * TILE_B;
    constexpr uint32_t AH_OFF = 0;
    constexpr uint32_t AL_OFF = (NP >= 2) ? TILE_B : 0;
    constexpr uint32_t BH_OFF = (NP >= 2) ? 2 * TILE_B : TILE_B;
    constexpr uint32_t BL_OFF = 3 * TILE_B;
    constexpr int CPR = KC / 8;  // 16B chunks per row
    constexpr int NCHUNK = 128 * CPR;
    constexpr int NK16 = KC / 16;

    extern __shared__ char smem[];
    const uint32_t sb = smem_u32(smem);
    const int tid = threadIdx.x;
    const int lane = tid & 31, wid = tid >> 5;
    const int wm = wid & 3, wn = wid >> 2;
    const int n0 = blockIdx.x * 128, m0 = blockIdx.y * 128, bz = blockIdx.z;

    const __half* A_h = Ah + (size_t)bz * a_batch + (size_t)m0 * a_row;
    const __half* A_l = (NP >= 2) ? (Al + (size_t)bz * a_batch + (size_t)m0 * a_row) : nullptr;
    const __half* B_h = Bh + (size_t)bz * b_batch + (size_t)n0 * b_row;
    const __half* B_l = (NP == 3) ? (Bl + (size_t)bz * b_batch + (size_t)n0 * b_row) : nullptr;

    auto swz = [](int r, int c16) {
        return (KC == 32) ? sw_off32(r, c16) : sw_off64(r, c16);
    };

    auto load_tile = [&](uint32_t dst, const __half* g, size_t rstride, int kk) {
#pragma unroll
        for (int i = tid; i < NCHUNK; i += 256) {
            const int r = i / CPR, cc = i % CPR;
            const char* gp = (const char*)(g + (size_t)r * rstride + kk) + (cc << 4);
            asm volatile("cp.async.cg.shared.global [%0], [%1], 16;"
                         :: "r"(dst + swz(r, cc)), "l"(gp) : "memory");
        }
    };
    auto load_stage = [&](int c) {
        const int kk = c * KC;
        const uint32_t st = sb + (uint32_t)(c % NSTG) * STAGE_B;
        load_tile(st + AH_OFF, A_h, a_row, kk);
        if (NP >= 2) load_tile(st + AL_OFF, A_l, a_row, kk);
        load_tile(st + BH_OFF, B_h, b_row, kk);
        if (NP == 3) load_tile(st + BL_OFF, B_l, b_row, kk);
        asm volatile("cp.async.commit_group;" ::: "memory");
    };

    // per-thread ldmatrix offsets (k16 step j via XOR j<<5)
    uint32_t offA[2], offB[4];
    {
        const int gA = lane >> 4;
#pragma unroll
        for (int mi = 0; mi < 2; mi++)
            offA[mi] = swz(wm * 32 + mi * 16 + (lane & 15), gA);
        const int gB = (lane >> 3) & 1;
        const int rb = wn * 64 + ((lane >> 4) << 3) + (lane & 7);
#pragma unroll
        for (int nj = 0; nj < 4; nj++) offB[nj] = swz(rb + nj * 16, gB);
    }

    float acc[2][8][4];
#pragma unroll
    for (int i = 0; i < 2; i++)
#pragma unroll
        for (int j = 0; j < 8; j++)
#pragma unroll
            for (int q = 0; q < 4; q++) acc[i][j][q] = 0.0f;

#pragma unroll
    for (int s = 0; s < NSTG - 1; s++) load_stage(s);

    for (int c = 0; c < KCH; c++) {
        asm volatile("cp.async.wait_group %0;" :: "n"(NSTG - 2) : "memory");
        __syncthreads();
        if (c + NSTG - 1 < KCH) load_stage(c + NSTG - 1);
        else asm volatile("cp.async.commit_group;" ::: "memory");

        const uint32_t st = sb + (uint32_t)(c % NSTG) * STAGE_B;
#pragma unroll
        for (int k16 = 0; k16 < NK16; k16++) {
            const uint32_t x = (uint32_t)(k16 << 5);
            uint32_t ah[2][4], al[2][4];
            ldsm4(ah[0], st + AH_OFF + (offA[0] ^ x));
            ldsm4(ah[1], st + AH_OFF + (offA[1] ^ x));
            if (NP >= 2) {
                ldsm4(al[0], st + AL_OFF + (offA[0] ^ x));
                ldsm4(al[1], st + AL_OFF + (offA[1] ^ x));
            }
#pragma unroll
            for (int nj = 0; nj < 4; nj++) {
                uint32_t bh[4];
                ldsm4(bh, st + BH_OFF + (offB[nj] ^ x));
                mma_f16(acc[0][2 * nj], ah[0], bh[0], bh[1]);
                mma_f16(acc[0][2 * nj + 1], ah[0], bh[2], bh[3]);
                mma_f16(acc[1][2 * nj], ah[1], bh[0], bh[1]);
                mma_f16(acc[1][2 * nj + 1], ah[1], bh[2], bh[3]);
                if (NP >= 2) {
                    mma_f16(acc[0][2 * nj], al[0], bh[0], bh[1]);
                    mma_f16(acc[0][2 * nj + 1], al[0], bh[2], bh[3]);
                    mma_f16(acc[1][2 * nj], al[1], bh[0], bh[1]);
                    mma_f16(acc[1][2 * nj + 1], al[1], bh[2], bh[3]);
                }
                if (NP == 3) {
                    uint32_t bl[4];
                    ldsm4(bl, st + BL_OFF + (offB[nj] ^ x));
                    mma_f16(acc[0][2 * nj], ah[0], bl[0], bl[1]);
                    mma_f16(acc[0][2 * nj + 1], ah[0], bl[2], bl[3]);
                    mma_f16(acc[1][2 * nj], ah[1], bl[0], bl[1]);
                    mma_f16(acc[1][2 * nj + 1], ah[1], bl[2], bl[3]);
                }
            }
        }
    }

    // -------- epilogue --------
    const int trow = lane >> 2, tcol = (lane & 3) * 2;
#pragma unroll
    for (int mi = 0; mi < 2; mi++) {
#pragma unroll
        for (int nj = 0; nj < 8; nj++) {
            const int row = m0 + wm * 32 + mi * 16 + trow;
            const int col = n0 + wn * 64 + nj * 8 + tcol;
            const float* a4 = acc[mi][nj];
            if (EPI == 0) {
                float* p = outF + (size_t)bz * c_batch + (size_t)row * c_row + col;
                *(float2*)p = make_float2(a4[0], a4[1]);
                *(float2*)(p + 8 * c_row) = make_float2(a4[2], a4[3]);
            } else if (EPI == 1) {
                __half* ph = outH + (size_t)bz * c_batch + (size_t)row * c_row + col;
                __half2 vh;
                vh.x = __float2half_rn(a4[0]);
                vh.y = __float2half_rn(a4[1]);
                *(__half2*)ph = vh;
                vh.x = __float2half_rn(a4[2]);
                vh.y = __float2half_rn(a4[3]);
                *(__half2*)(ph + 8 * c_row) = vh;
            } else {
                const float b0 = bias[col], b1 = bias[col + 1];
                float* p = outF + (size_t)bz * c_batch + (size_t)row * c_row + col;
                *(float2*)p = make_float2(tanhf(a4[0] + b0), tanhf(a4[1] + b1));
                *(float2*)(p + 8 * c_row) = make_float2(tanhf(a4[2] + b0), tanhf(a4[3] + b1));
            }
        }
    }
}

// ---------------- conversion kernels (vectorized) ----------------
__global__ __launch_bounds__(256) void conv_q(const float* __restrict__ Q) {
    size_t i4 = ((size_t)blockIdx.x * 256 + threadIdx.x) * 4;  // over T*B*D
    float4 v = *(const float4*)(Q + i4);
    int d = (int)(i4 & (DD - 1));
    size_t j = i4 >> 10;
    int b = (int)(j & (BB - 1));
    size_t t = j >> 4;
    size_t o = ((size_t)b * TT + t) * KK2 + DD + d;
    __half h0, l0, h1, l1;
    __half2 vh, vl;
    split2(v.x, h0, l0); split2(v.y, h1, l1);
    vh.x = h0; vh.y = h1; vl.x = l0; vl.y = l1;
    *(__half2*)(g_combH + o) = vh;
    *(__half2*)(g_combL + o) = vl;
    split2(v.z, h0, l0); split2(v.w, h1, l1);
    vh.x = h0; vh.y = h1; vl.x = l0; vl.y = l1;
    *(__half2*)(g_combH + o + 2) = vh;
    *(__half2*)(g_combL + o + 2) = vl;
}

__global__ __launch_bounds__(256) void conv_c_ct(const float* __restrict__ C) {
    __shared__ float tile[32][33];
    const int b = blockIdx.z;
    const int d0 = blockIdx.x * 32, s0 = blockIdx.y * 32;
    const int tx = threadIdx.x, ty = threadIdx.y;  // (32,8)
#pragma unroll
    for (int i = 0; i < 4; i++) {
        int s = s0 + ty + i * 8;
        float v = C[((size_t)s * BB + b) * DD + d0 + tx];
        tile[ty + i * 8][tx] = v;
        size_t o = ((size_t)b * SS + s) * DD + d0 + tx;
        g_cH[o] = __float2half_rn(v);
    }
    __syncthreads();
#pragma unroll
    for (int i = 0; i < 4; i++) {
        int d = d0 + ty + i * 8;
        size_t o = ((size_t)b * DD + d) * SS + s0 + tx;
        g_cTH[o] = __float2half_rn(tile[tx][ty + i * 8]);
    }
}

__global__ __launch_bounds__(256) void conv_w(const float* __restrict__ W) {
    size_t i4 = ((size_t)blockIdx.x * 256 + threadIdx.x) * 4;  // over D*2D
    float4 v = *(const float4*)(W + i4);
    __half2 vh;
    vh.x = __float2half_rn(v.x);
    vh.y = __float2half_rn(v.y);
    *(__half2*)(g_WH + i4) = vh;
    vh.x = __float2half_rn(v.z);
    vh.y = __float2half_rn(v.w);
    *(__half2*)(g_WH + i4 + 2) = vh;
}

// ---------------- softmax (==0 -> -inf mask), fp32 scores -> fp16 probs ----------------
__global__ __launch_bounds__(256) void softmax_mask() {
    const size_t rowi = blockIdx.x;
    const float4* p4 = (const float4*)(g_scores + rowi * SS);
    __half2* ph2 = (__half2*)(g_PH + rowi * SS);
    const int tid = threadIdx.x;
    __shared__ float red[256];
    float4 v[2];
    float m = -INFINITY;
#pragma unroll
    for (int i = 0; i < 2; i++) {
        v[i] = p4[tid + i * 256];
        float* f = (float*)&v[i];
#pragma unroll
        for (int q = 0; q < 4; q++) {
            float x = (f[q] == 0.0f) ? -INFINITY : f[q];
            m = fmaxf(m, x);
        }
    }
    red[tid] = m;
    __syncthreads();
#pragma unroll
    for (int s = 128; s > 0; s >>= 1) {
        if (tid < s) red[tid] = fmaxf(red[tid], red[tid + s]);
        __syncthreads();
    }
    m = red[0];
    __syncthreads();
    float e[8];
    float sum = 0.0f;
#pragma unroll
    for (int i = 0; i < 2; i++) {
        float* f = (float*)&v[i];
#pragma unroll
        for (int q = 0; q < 4; q++) {
            float x = (f[q] == 0.0f) ? 0.0f : __expf(f[q] - m);
            e[i * 4 + q] = x;
            sum += x;
        }
    }
    red[tid] = sum;
    __syncthreads();
#pragma unroll
    for (int s = 128; s > 0; s >>= 1) {
        if (tid < s) red[tid] += red[tid + s];
        __syncthreads();
    }
    const float inv = 1.0f / red[0];
#pragma unroll
    for (int i = 0; i < 2; i++) {
#pragma unroll
        for (int q = 0; q < 2; q++) {
            __half2 vh;
            vh.x = __float2half_rn(e[i * 4 + q * 2] * inv);
            vh.y = __float2half_rn(e[i * 4 + q * 2 + 1] * inv);
            ph2[(tid + i * 256) * 2 + q] = vh;
        }
    }
}

// ---------------- launch ----------------
#define SMEM_G1 98304   // NP2 KC64: 2 stages x 48KB
#define SMEM_G23 98304  // NP1 KC64: 3 stages x 32KB

extern "C" void kernel_launch(void* const* d_in, const int* in_sizes, int n_in,
                              void* d_out, int out_size) {
    (void)in_sizes; (void)n_in; (void)out_size;
    const float* Q = (const float*)d_in[0];
    const float* C = (const float*)d_in[1];
    const float* W = (const float*)d_in[2];
    const float* bias = (const float*)d_in[3];
    float* out = (float*)d_out;

    void *pScores, *pCombH, *pCombL, *pCH, *pCTH, *pPH, *pWH;
    cudaGetSymbolAddress(&pScores, g_scores);
    cudaGetSymbolAddress(&pCombH, g_combH);
    cudaGetSymbolAddress(&pCombL, g_combL);
    cudaGetSymbolAddress(&pCH, g_cH);
    cudaGetSymbolAddress(&pCTH, g_cTH);
    cudaGetSymbolAddress(&pPH, g_PH);
    cudaGetSymbolAddress(&pWH, g_WH);

    cudaFuncSetAttribute((const void*)mma_gemm<0, 2, 64>, cudaFuncAttributeMaxDynamicSharedMemorySize, SMEM_G1);
    cudaFuncSetAttribute((const void*)mma_gemm<1, 1, 64>, cudaFuncAttributeMaxDynamicSharedMemorySize, SMEM_G23);
    cudaFuncSetAttribute((const void*)mma_gemm<2, 1, 64>, cudaFuncAttributeMaxDynamicSharedMemorySize, SMEM_G23);

    // conversions
    conv_q<<<(unsigned)((size_t)TT * BB * DD / 1024), 256>>>(Q);
    conv_c_ct<<<dim3(DD / 32, SS / 32, BB), dim3(32, 8)>>>(C);
    conv_w<<<(unsigned)((size_t)DD * KK2 / 1024), 256>>>(W);

    // GEMM1: scores = q . c   (2-pass: qh*ch + ql*ch, KC64/NSTG2)
    mma_gemm<0, 2, 64><<<dim3(SS / 128, TT / 128, BB), 256, SMEM_G1>>>(
        (const __half*)pCombH + DD, (const __half*)pCombL + DD,
        (size_t)KK2, (size_t)TT * KK2,
        (const __half*)pCH, nullptr,
        (size_t)DD, (size_t)SS * DD,
        DD / 64,
        (float*)pScores, nullptr, (size_t)SS, (size_t)TT * SS, nullptr);

    softmax_mask<<<BB * TT, 256>>>();

    // GEMM2: mix = P . cT   (1-pass fp16, KC64/NSTG3) -> fp16 into comb cols [0,1024)
    mma_gemm<1, 1, 64><<<dim3(DD / 128, TT / 128, BB), 256, SMEM_G23>>>(
        (const __half*)pPH, nullptr,
        (size_t)SS, (size_t)TT * SS,
        (const __half*)pCTH, nullptr,
        (size_t)SS, (size_t)DD * SS,
        SS / 64,
        nullptr, (__half*)pCombH, (size_t)KK2, (size_t)TT * KK2, nullptr);

    // GEMM3: out = tanh(comb . W^T + bias)   (1-pass fp16, KC64/NSTG3)
    mma_gemm<2, 1, 64><<<dim3(DD / 128, TT / 128, BB), 256, SMEM_G23>>>(
        (const __half*)pCombH, nullptr,
        (size_t)KK2, (size_t)TT * KK2,
        (const __half*)pWH, nullptr,
        (size_t)KK2, (size_t)0,
        KK2 / 64,
        out, nullptr, (size_t)DD, (size_t)TT * DD, bias);
}